// round 16
// baseline (speedup 1.0000x reference)
#include <cuda_runtime.h>
#include <cuda_bf16.h>
#include <math.h>

#define SS 2048
#define BB 64
#define IIN 256
#define HHID 512
#define EEMB 256
#define BH (BB*HHID)
#define OUT_HT ((size_t)SS*BH)
#define OUT_MT (OUT_HT+BH)
#define REC_SMEM 65536
#define NREC 16
#define NWORK 132

__device__ float g_Wc[HHID*HHID];
__device__ float g_bvec[HHID];
// h planes, MMA-fragment layout: [chain][slot][mtile*1024 + ks*32 + lane]
__device__ uint4 g_F1[2][2][4096];
__device__ uint4 g_F2[2][2][4096];
__device__ unsigned g_flag[2][16*32];
__device__ unsigned g_ready[SS];
__device__ unsigned g_done;

__device__ __forceinline__ void split2(float a,float b,unsigned&hi,unsigned&lo){
    __nv_bfloat16 ah=__float2bfloat16_rn(a), bh=__float2bfloat16_rn(b);
    __nv_bfloat162 H; H.x=ah; H.y=bh;
    __nv_bfloat162 L=__floats2bfloat162_rn(a-__bfloat162float(ah), b-__bfloat162float(bh));
    hi=*reinterpret_cast<unsigned*>(&H); lo=*reinterpret_cast<unsigned*>(&L);
}
__device__ __forceinline__ void mma4(float&d0,float&d1,float&d2,float&d3,
    unsigned a0,unsigned a1,unsigned a2,unsigned a3,unsigned b0,unsigned b1){
    asm volatile("mma.sync.aligned.m16n8k16.row.col.f32.bf16.bf16.f32 "
        "{%0,%1,%2,%3},{%4,%5,%6,%7},{%8,%9},{%0,%1,%2,%3};\n"
        :"+f"(d0),"+f"(d1),"+f"(d2),"+f"(d3)
        :"r"(a0),"r"(a1),"r"(a2),"r"(a3),"r"(b0),"r"(b1));
}
__device__ __forceinline__ void st_release(unsigned*p,unsigned v){
    asm volatile("st.global.release.gpu.u32 [%0],%1;"::"l"(p),"r"(v):"memory");
}
__device__ __forceinline__ unsigned ld_flag(const unsigned*p){
    unsigned v; asm volatile("ld.global.acquire.gpu.u32 %0,[%1];":"=r"(v):"l"(p):"memory");
    return v;
}
__device__ __forceinline__ void red_release(unsigned*p,unsigned v){
    asm volatile("red.release.gpu.global.add.u32 [%0],%1;"::"l"(p),"r"(v):"memory");
}

// ---- prep ----
__global__ __launch_bounds__(256) void prep_kernel(
    const float* __restrict__ W_ih,const float* __restrict__ W_embed,
    const float* __restrict__ b_ih,const float* __restrict__ b_embed){
    __shared__ float wm[EEMB];
    int h1=blockIdx.x, tid=threadIdx.x;
    wm[tid]=W_ih[(size_t)h1*(IIN+EEMB)+IIN+tid];
    __syncthreads();
    float a0=0.f,a1=0.f;
    #pragma unroll 4
    for(int e=0;e<EEMB;e++){
        float w=wm[e];
        a0=fmaf(w,W_embed[(size_t)e*HHID+tid],a0);
        a1=fmaf(w,W_embed[(size_t)e*HHID+tid+256],a1);
    }
    g_Wc[(size_t)h1*HHID+tid]=a0;
    g_Wc[(size_t)h1*HHID+tid+256]=a1;
    if(tid==0){
        float s=b_ih[h1];
        for(int e=0;e<EEMB;e++) s=fmaf(wm[e],b_embed[e],s);
        g_bvec[h1]=s;
    }
}

__device__ __forceinline__ void seed_elem(int chain,int b,int h,float val){
    int mt=b>>4, g=b&7, rp=(b>>3)&1;
    int ks=h>>4, rem=h&15, sl=rem>>3, qi=(rem&7)>>1, p=rem&1;
    int off=(mt*1024+ks*32+(g*4+qi))*16 + sl*8 + rp*4 + p*2;
    __nv_bfloat16 hi=__float2bfloat16_rn(val);
    __nv_bfloat16 lo=__float2bfloat16_rn(val-__bfloat162float(hi));
    *(__nv_bfloat16*)((char*)g_F1[chain][0]+off)=hi;
    *(__nv_bfloat16*)((char*)g_F2[chain][0]+off)=lo;
}

// ---- boot ----
__global__ __launch_bounds__(64) void boot_kernel(
    const float* __restrict__ x,const float* __restrict__ h0,
    const float* __restrict__ m0,const float* __restrict__ W_ih,
    const float* __restrict__ b_ih,float* __restrict__ out){
    __shared__ float wx[IIN], wm[EEMB];
    int h=blockIdx.x, b=threadIdx.x;
    if(h<SS/4 && b<4) g_ready[h*4+b]=0;
    if(h==0){
        if(b<16) g_flag[0][b*32]=0;
        else if(b<32) g_flag[1][(b-16)*32]=0;
        else if(b==32) g_done=0;
    }
    for(int e=b;e<IIN;e+=64) wx[e]=W_ih[(size_t)h*(IIN+EEMB)+e];
    for(int e=b;e<EEMB;e+=64) wm[e]=W_ih[(size_t)h*(IIN+EEMB)+IIN+e];
    __syncthreads();
    float acc=b_ih[h];
    const float* xr=x+(size_t)b*IIN;
    const float* mr=m0+(size_t)b*EEMB;
    #pragma unroll 4
    for(int k=0;k<IIN;k++) acc=fmaf(wx[k],xr[k],acc);
    #pragma unroll 4
    for(int e=0;e<EEMB;e++) acc=fmaf(wm[e],mr[e],acc);
    int idx=b*HHID+h;
    float v=tanhf(acc);
    out[idx]=v;
    seed_elem(0,b,h,v);
    seed_elem(1,b,h,h0[idx]);
}

// ---- worker P tile ----
__device__ void p_tile(const float* __restrict__ x,const float* __restrict__ W,
    float* __restrict__ out,int m0,int n0,float (*As)[68],float (*Bs)[68]){
    int tid=threadIdx.x, tx=tid&15, ty=tid>>4;
    float acc[4][4];
    #pragma unroll
    for(int i=0;i<4;i++)
        #pragma unroll
        for(int j=0;j<4;j++) acc[i][j]=0.f;
    for(int k0=0;k0<IIN;k0+=32){
        #pragma unroll
        for(int i=0;i<2;i++){
            int f=tid+i*256, row=f>>3, kq=(f&7)<<2;
            float4 v=*reinterpret_cast<const float4*>(x+(size_t)(m0+row)*IIN+k0+kq);
            As[kq][row]=v.x;As[kq+1][row]=v.y;As[kq+2][row]=v.z;As[kq+3][row]=v.w;
            float4 w=*reinterpret_cast<const float4*>(W+(size_t)(n0+row)*(IIN+EEMB)+k0+kq);
            Bs[kq][row]=w.x;Bs[kq+1][row]=w.y;Bs[kq+2][row]=w.z;Bs[kq+3][row]=w.w;
        }
        __syncthreads();
        #pragma unroll
        for(int k=0;k<32;k++){
            float4 a=*reinterpret_cast<const float4*>(&As[k][ty*4]);
            float4 b=*reinterpret_cast<const float4*>(&Bs[k][tx*4]);
            float av[4]={a.x,a.y,a.z,a.w}, bv[4]={b.x,b.y,b.z,b.w};
            #pragma unroll
            for(int i=0;i<4;i++)
                #pragma unroll
                for(int j=0;j<4;j++) acc[i][j]=fmaf(av[i],bv[j],acc[i][j]);
        }
        __syncthreads();
    }
    #pragma unroll
    for(int i=0;i<4;i++){
        float4 v=make_float4(acc[i][0],acc[i][1],acc[i][2],acc[i][3]);
        *reinterpret_cast<float4*>(out+(size_t)(m0+ty*4+i)*HHID+n0+tx*4)=v;
    }
}

// ---- fused: 16 dual-chain rec CTAs + 132 P workers ----
__global__ void __launch_bounds__(256,1) fused_kernel(
    const float* __restrict__ x,const float* __restrict__ W_ih,
    float* __restrict__ out){
    extern __shared__ char smc[];
    const int tid=threadIdx.x, bid=blockIdx.x;

    if(bid>=NREC){
        float (*As)[68]=(float(*)[68])smc;
        float (*Bs)[68]=(float(*)[68])(smc+8704);
        int wbid=bid-NREC;
        for(int u=wbid; u<(SS-1)*4; u+=NWORK){
            int t=1+(u>>2), q=u&3;
            p_tile(x,W_ih,out,t*64,q*128,As,Bs);
            p_tile(x,W_ih,out,t*64,q*128+64,As,Bs);
            __syncthreads();
            if(tid==0) red_release(&g_ready[t],1u);
        }
        volatile unsigned* dp=&g_done;
        while(*dp!=(unsigned)NREC){ }
        return;
    }

    // ---- rec CTA: owns 32 cols of BOTH chains ----
    uint2* Bf1=(uint2*)smc;            // [ng4][ks32][lane32]
    uint2* Bf2=(uint2*)(smc+32768);
    const int lane=tid&31, wid=tid>>5;
    const int chain=wid>>2;            // warps 0-3: chain0, 4-7: chain1
    const int mtile=wid&3;
    const int cta=bid, col0=cta*32;
    const int qi=lane&3;
    const int r0=mtile*16+(lane>>2);

    for(int idx=tid;idx<4096;idx+=256){
        int ng=idx>>10, rem=idx&1023, ks=rem>>5, ln=rem&31;
        int n=col0+ng*8+(ln>>2), k=ks*16+(ln&3)*2;
        const float* wr=g_Wc+(size_t)n*HHID+k;
        unsigned h0v,l0v,h1v,l1v;
        split2(wr[0],wr[1],h0v,l0v);
        split2(wr[8],wr[9],h1v,l1v);
        Bf1[idx]=make_uint2(h0v,h1v);
        Bf2[idx]=make_uint2(l0v,l1v);
    }
    float bs[4][2];
    #pragma unroll
    for(int n=0;n<4;n++){
        int c=col0+n*8+2*qi;
        bs[n][0]=g_bvec[c]; bs[n][1]=g_bvec[c+1];
    }
    const uint2* Bp1[4]; const uint2* Bp2[4];
    #pragma unroll
    for(int n=0;n<4;n++){ Bp1[n]=Bf1+n*1024+lane; Bp2[n]=Bf2+n*1024+lane; }
    const int fo=mtile*1024+lane;
    const int wk0=mtile*1024+(cta*2)*32+lane, wk1=wk0+32;
    const int n_it=1023+chain;
    const int barid=1+chain;
    __syncthreads();

    for(int i=0;i<n_it;i++){
        int t=2*i+2-chain;
        int rs=i&1, ws=rs^1;
        const uint4* Fp1=g_F1[chain][rs];
        const uint4* Fp2=g_F2[chain][rs];
        // wait P[t] ready (chain's poller warp)
        if(wid==chain*4){
            unsigned v;
            do{ v=ld_flag(&g_ready[t]); } while(__any_sync(0xffffffffu, v<4u));
        }
        asm volatile("bar.sync %0,128;"::"r"(barid):"memory");
        // P loads
        size_t oaddr[4]; float2 P0[4],P1[4];
        #pragma unroll
        for(int n=0;n<4;n++){
            oaddr[n]=(size_t)t*BH+(size_t)r0*HHID+col0+n*8+2*qi;
            P0[n]=__ldcg((const float2*)(out+oaddr[n]));
            P1[n]=__ldcg((const float2*)(out+oaddr[n]+8*HHID));
        }
        float acc[4][4];
        #pragma unroll
        for(int n=0;n<4;n++){acc[n][0]=0.f;acc[n][1]=0.f;acc[n][2]=0.f;acc[n][3]=0.f;}
        uint4 f1c=__ldcg(Fp1+fo), f2c=__ldcg(Fp2+fo);
        #pragma unroll
        for(int ks=0;ks<32;ks++){
            uint4 f1n,f2n;
            if(ks<31){ f1n=__ldcg(Fp1+fo+(ks+1)*32); f2n=__ldcg(Fp2+fo+(ks+1)*32); }
            #pragma unroll
            for(int n=0;n<4;n++){
                uint2 w1=Bp1[n][ks*32], w2=Bp2[n][ks*32];
                mma4(acc[n][0],acc[n][1],acc[n][2],acc[n][3],
                     f1c.x,f1c.y,f1c.z,f1c.w, w1.x,w1.y);
                mma4(acc[n][0],acc[n][1],acc[n][2],acc[n][3],
                     f1c.x,f1c.y,f1c.z,f1c.w, w2.x,w2.y);
                mma4(acc[n][0],acc[n][1],acc[n][2],acc[n][3],
                     f2c.x,f2c.y,f2c.z,f2c.w, w1.x,w1.y);
            }
            f1c=f1n; f2c=f2n;
        }
        // finalize
        float v[4][4];
        #pragma unroll
        for(int n=0;n<4;n++){
            v[n][0]=tanhf(P0[n].x+bs[n][0]+acc[n][0]);
            v[n][1]=tanhf(P0[n].y+bs[n][1]+acc[n][1]);
            v[n][2]=tanhf(P1[n].x+bs[n][0]+acc[n][2]);
            v[n][3]=tanhf(P1[n].y+bs[n][1]+acc[n][3]);
        }
        // plane writes first (ordered before flag release)
        uint4 H1,L1,H2,L2;
        split2(v[0][0],v[0][1],H1.x,L1.x); split2(v[0][2],v[0][3],H1.y,L1.y);
        split2(v[1][0],v[1][1],H1.z,L1.z); split2(v[1][2],v[1][3],H1.w,L1.w);
        split2(v[2][0],v[2][1],H2.x,L2.x); split2(v[2][2],v[2][3],H2.y,L2.y);
        split2(v[3][0],v[3][1],H2.z,L2.z); split2(v[3][2],v[3][3],H2.w,L2.w);
        g_F1[chain][ws][wk0]=H1; g_F2[chain][ws][wk0]=L1;
        g_F1[chain][ws][wk1]=H2; g_F2[chain][ws][wk1]=L2;
        asm volatile("bar.sync %0,128;"::"r"(barid):"memory");
        if(tid==chain*128){ st_release(&g_flag[chain][cta*32],(unsigned)(i+1)); }
        // out stores after flag (consumed only by fin)
        #pragma unroll
        for(int n=0;n<4;n++){
            *(float2*)(out+oaddr[n])=make_float2(v[n][0],v[n][1]);
            *(float2*)(out+oaddr[n]+8*HHID)=make_float2(v[n][2],v[n][3]);
        }
        // wait all 16 CTAs of this chain
        if(wid==chain*4){
            const unsigned* fp=&g_flag[chain][(lane&15)*32];
            unsigned vv;
            do { vv=ld_flag(fp); } while(!__all_sync(0xffffffffu, vv>(unsigned)i));
        }
        asm volatile("bar.sync %0,128;"::"r"(barid):"memory");
    }
    __syncthreads();
    if(tid==0) red_release(&g_done,1u);
}

// ---- fin ----
__global__ __launch_bounds__(256) void fin_kernel(
    const float* __restrict__ W_embed,const float* __restrict__ b_embed,
    float* __restrict__ out){
    __shared__ float hsr[HHID];
    int b=blockIdx.x, e=threadIdx.x;
    hsr[e]=out[(size_t)2046*BH+(size_t)b*HHID+e];
    hsr[e+256]=out[(size_t)2046*BH+(size_t)b*HHID+e+256];
    out[OUT_HT+(size_t)b*HHID+e]=out[(size_t)2047*BH+(size_t)b*HHID+e];
    out[OUT_HT+(size_t)b*HHID+e+256]=out[(size_t)2047*BH+(size_t)b*HHID+e+256];
    __syncthreads();
    float acc=b_embed[e];
    const float* we=W_embed+(size_t)e*HHID;
    #pragma unroll 4
    for(int h=0;h<HHID;h++) acc=fmaf(hsr[h],we[h],acc);
    out[OUT_MT+(size_t)b*EEMB+e]=acc;
}

extern "C" void kernel_launch(void* const* d_in,const int* in_sizes,int n_in,
                              void* d_out,int out_size){
    const float* input_seq=(const float*)d_in[0];
    const float* h_0=(const float*)d_in[1];
    const float* m_0=(const float*)d_in[2];
    const float* W_embed=(const float*)d_in[3];
    const float* b_embed=(const float*)d_in[4];
    const float* W_ih=(const float*)d_in[5];
    const float* b_ih=(const float*)d_in[6];
    float* out=(float*)d_out;

    cudaFuncSetAttribute(fused_kernel,cudaFuncAttributeMaxDynamicSharedMemorySize,REC_SMEM);
    prep_kernel<<<HHID,256>>>(W_ih,W_embed,b_ih,b_embed);
    boot_kernel<<<HHID,64>>>(input_seq,h_0,m_0,W_ih,b_ih,out);
    fused_kernel<<<NREC+NWORK,256,REC_SMEM>>>(input_seq,W_ih,out);
    fin_kernel<<<BB,256>>>(W_embed,b_embed,out);
}

// round 17
// speedup vs baseline: 1.8452x; 1.8452x over previous
#include <cuda_runtime.h>
#include <cuda_bf16.h>
#include <math.h>

#define SS 2048
#define BB 64
#define IIN 256
#define HHID 512
#define EEMB 256
#define BH (BB*HHID)
#define OUT_HT ((size_t)SS*BH)
#define OUT_MT (OUT_HT+BH)
// Bf1 64K | Bf2 64K | red 16K
#define REC_SMEM 147456
#define NREC 64
#define NWORK 84

__device__ float g_Wc[HHID*HHID];
__device__ float g_bvec[HHID];
// h planes, MMA-fragment layout: [parity][slot][bgroup*1024 + ks*32 + lane]
__device__ uint4 g_F1[2][2][4096];
__device__ uint4 g_F2[2][2][4096];
__device__ unsigned g_flag2[16][8*32];   // [domain][cta8*32]
__device__ unsigned g_ready[SS];
__device__ unsigned g_done;

__device__ __forceinline__ void split2(float a,float b,unsigned&hi,unsigned&lo){
    __nv_bfloat16 ah=__float2bfloat16_rn(a), bh=__float2bfloat16_rn(b);
    __nv_bfloat162 H; H.x=ah; H.y=bh;
    __nv_bfloat162 L=__floats2bfloat162_rn(a-__bfloat162float(ah), b-__bfloat162float(bh));
    hi=*reinterpret_cast<unsigned*>(&H); lo=*reinterpret_cast<unsigned*>(&L);
}
__device__ __forceinline__ void mma4(float&d0,float&d1,float&d2,float&d3,
    unsigned a0,unsigned a1,unsigned a2,unsigned a3,unsigned b0,unsigned b1){
    asm volatile("mma.sync.aligned.m16n8k16.row.col.f32.bf16.bf16.f32 "
        "{%0,%1,%2,%3},{%4,%5,%6,%7},{%8,%9},{%0,%1,%2,%3};\n"
        :"+f"(d0),"+f"(d1),"+f"(d2),"+f"(d3)
        :"r"(a0),"r"(a1),"r"(a2),"r"(a3),"r"(b0),"r"(b1));
}
__device__ __forceinline__ void st_release(unsigned*p,unsigned v){
    asm volatile("st.global.release.gpu.u32 [%0],%1;"::"l"(p),"r"(v):"memory");
}
__device__ __forceinline__ unsigned ld_flag(const unsigned*p){
    unsigned v; asm volatile("ld.global.acquire.gpu.u32 %0,[%1];":"=r"(v):"l"(p):"memory");
    return v;
}
__device__ __forceinline__ void red_release(unsigned*p,unsigned v){
    asm volatile("red.release.gpu.global.add.u32 [%0],%1;"::"l"(p),"r"(v):"memory");
}

// ---- prep ----
__global__ __launch_bounds__(256) void prep_kernel(
    const float* __restrict__ W_ih,const float* __restrict__ W_embed,
    const float* __restrict__ b_ih,const float* __restrict__ b_embed){
    __shared__ float wm[EEMB];
    int h1=blockIdx.x, tid=threadIdx.x;
    wm[tid]=W_ih[(size_t)h1*(IIN+EEMB)+IIN+tid];
    __syncthreads();
    float a0=0.f,a1=0.f;
    #pragma unroll 4
    for(int e=0;e<EEMB;e++){
        float w=wm[e];
        a0=fmaf(w,W_embed[(size_t)e*HHID+tid],a0);
        a1=fmaf(w,W_embed[(size_t)e*HHID+tid+256],a1);
    }
    g_Wc[(size_t)h1*HHID+tid]=a0;
    g_Wc[(size_t)h1*HHID+tid+256]=a1;
    if(tid==0){
        float s=b_ih[h1];
        for(int e=0;e<EEMB;e++) s=fmaf(wm[e],b_embed[e],s);
        g_bvec[h1]=s;
    }
}

__device__ __forceinline__ void seed_elem(int chain,int b,int h,float val){
    int mt=b>>4, g=b&7, rp=(b>>3)&1;
    int ks=h>>4, rem=h&15, sl=rem>>3, qi=(rem&7)>>1, p=rem&1;
    int off=(mt*1024+ks*32+(g*4+qi))*16 + sl*8 + rp*4 + p*2;
    __nv_bfloat16 hi=__float2bfloat16_rn(val);
    __nv_bfloat16 lo=__float2bfloat16_rn(val-__bfloat162float(hi));
    *(__nv_bfloat16*)((char*)g_F1[chain][0]+off)=hi;
    *(__nv_bfloat16*)((char*)g_F2[chain][0]+off)=lo;
}

// ---- boot ----
__global__ __launch_bounds__(64) void boot_kernel(
    const float* __restrict__ x,const float* __restrict__ h0,
    const float* __restrict__ m0,const float* __restrict__ W_ih,
    const float* __restrict__ b_ih,float* __restrict__ out){
    __shared__ float wx[IIN], wm[EEMB];
    int h=blockIdx.x, b=threadIdx.x;
    if(h<SS/4 && b<4) g_ready[h*4+b]=0;
    if(h==0){
        g_flag2[b>>3][(b&7)*32]=0;
        g_flag2[8+(b>>3)][(b&7)*32]=0;
        if(b==0) g_done=0;
    }
    for(int e=b;e<IIN;e+=64) wx[e]=W_ih[(size_t)h*(IIN+EEMB)+e];
    for(int e=b;e<EEMB;e+=64) wm[e]=W_ih[(size_t)h*(IIN+EEMB)+IIN+e];
    __syncthreads();
    float acc=b_ih[h];
    const float* xr=x+(size_t)b*IIN;
    const float* mr=m0+(size_t)b*EEMB;
    #pragma unroll 4
    for(int k=0;k<IIN;k++) acc=fmaf(wx[k],xr[k],acc);
    #pragma unroll 4
    for(int e=0;e<EEMB;e++) acc=fmaf(wm[e],mr[e],acc);
    int idx=b*HHID+h;
    float v=tanhf(acc);
    out[idx]=v;
    seed_elem(0,b,h,v);
    seed_elem(1,b,h,h0[idx]);
}

// ---- worker P tile ----
__device__ void p_tile(const float* __restrict__ x,const float* __restrict__ W,
    float* __restrict__ out,int m0,int n0,float (*As)[68],float (*Bs)[68]){
    int tid=threadIdx.x, tx=tid&15, ty=tid>>4;
    float acc[4][4];
    #pragma unroll
    for(int i=0;i<4;i++)
        #pragma unroll
        for(int j=0;j<4;j++) acc[i][j]=0.f;
    for(int k0=0;k0<IIN;k0+=32){
        #pragma unroll
        for(int i=0;i<2;i++){
            int f=tid+i*256, row=f>>3, kq=(f&7)<<2;
            float4 v=*reinterpret_cast<const float4*>(x+(size_t)(m0+row)*IIN+k0+kq);
            As[kq][row]=v.x;As[kq+1][row]=v.y;As[kq+2][row]=v.z;As[kq+3][row]=v.w;
            float4 w=*reinterpret_cast<const float4*>(W+(size_t)(n0+row)*(IIN+EEMB)+k0+kq);
            Bs[kq][row]=w.x;Bs[kq+1][row]=w.y;Bs[kq+2][row]=w.z;Bs[kq+3][row]=w.w;
        }
        __syncthreads();
        #pragma unroll
        for(int k=0;k<32;k++){
            float4 a=*reinterpret_cast<const float4*>(&As[k][ty*4]);
            float4 b=*reinterpret_cast<const float4*>(&Bs[k][tx*4]);
            float av[4]={a.x,a.y,a.z,a.w}, bv[4]={b.x,b.y,b.z,b.w};
            #pragma unroll
            for(int i=0;i<4;i++)
                #pragma unroll
                for(int j=0;j<4;j++) acc[i][j]=fmaf(av[i],bv[j],acc[i][j]);
        }
        __syncthreads();
    }
    #pragma unroll
    for(int i=0;i<4;i++){
        float4 v=make_float4(acc[i][0],acc[i][1],acc[i][2],acc[i][3]);
        *reinterpret_cast<float4*>(out+(size_t)(m0+ty*4+i)*HHID+n0+tx*4)=v;
    }
}

// ---- fused: 64 rec CTAs (2 parity x 4 bgroup x 8 col-CTAs) + 84 workers ----
__global__ void __launch_bounds__(256,1) fused_kernel(
    const float* __restrict__ x,const float* __restrict__ W_ih,
    float* __restrict__ out){
    extern __shared__ char smc[];
    const int tid=threadIdx.x, bid=blockIdx.x;

    if(bid>=NREC){
        float (*As)[68]=(float(*)[68])smc;
        float (*Bs)[68]=(float(*)[68])(smc+8704);
        int wbid=bid-NREC;
        for(int u=wbid; u<(SS-1)*4; u+=NWORK){
            int t=1+(u>>2), q=u&3;
            p_tile(x,W_ih,out,t*64,q*128,As,Bs);
            p_tile(x,W_ih,out,t*64,q*128+64,As,Bs);
            __syncthreads();
            if(tid==0) red_release(&g_ready[t],1u);
        }
        volatile unsigned* dp=&g_done;
        float xx=1.0f+(float)bid*1e-6f;
        while(*dp!=(unsigned)NREC){
            #pragma unroll
            for(int j=0;j<128;j++) xx=fmaf(xx,1.0000001f,1e-30f);
            asm volatile(""::"f"(xx));
        }
        return;
    }

    // ---- rec CTA ----
    uint2* Bf1=(uint2*)smc;                 // [ng8][ks32][lane32]
    uint2* Bf2=(uint2*)(smc+65536);
    float4* red=(float4*)(smc+131072);      // [wid8][ngl4][lane32]
    const int lane=tid&31, wid=tid>>5;
    const int parity=bid&1, bgroup=(bid>>1)&3, cta8=bid>>3;
    const int domain=parity*4+bgroup, col0=cta8*64;
    const int kq=wid&3, p=wid>>2;
    const int qi=lane&3;
    const int rg=bgroup*16+(lane>>2);       // global batch row
    const int ngf=p*4+kq;                   // finalized local ngroup
    const int cf=col0+ngf*8+2*qi;           // finalized global col

    // resident B fragments: Wc slice for 64 cols, hi+lo planes
    for(int idx=tid;idx<8192;idx+=256){
        int ng=idx>>10, rem=idx&1023, ks=rem>>5, ln=rem&31;
        int n=col0+ng*8+(ln>>2), k=ks*16+(ln&3)*2;
        const float* wr=g_Wc+(size_t)n*HHID+k;
        unsigned h0v,l0v,h1v,l1v;
        split2(wr[0],wr[1],h0v,l0v);
        split2(wr[8],wr[9],h1v,l1v);
        Bf1[idx]=make_uint2(h0v,h1v);
        Bf2[idx]=make_uint2(l0v,l1v);
    }
    const float bias0=g_bvec[cf], bias1=g_bvec[cf+1];
    const uint2* Bp1[4]; const uint2* Bp2[4];
    #pragma unroll
    for(int n=0;n<4;n++){
        Bp1[n]=Bf1+(p*4+n)*1024+lane;
        Bp2[n]=Bf2+(p*4+n)*1024+lane;
    }
    const int fo=bgroup*1024+kq*8*32+lane;  // this warp's 8 ks
    // plane write target (two warps share a uint4; each writes its 8B half)
    char* w1base=(char*)&g_F1[parity][0][bgroup*1024+(cta8*4+(ngf>>1))*32+lane]+(ngf&1)*8;
    char* w2base=(char*)&g_F2[parity][0][bgroup*1024+(cta8*4+(ngf>>1))*32+lane]+(ngf&1)*8;
    const size_t slotstride=(char*)g_F1[0][1]-(char*)g_F1[0][0];
    const int n_it=1023+parity;
    __syncthreads();

    for(int i=0;i<n_it;i++){
        int t=2*i+2-parity;
        int rs=i&1, ws=rs^1;
        const uint4* Fp1=g_F1[parity][rs];
        const uint4* Fp2=g_F2[parity][rs];
        // wait P[t] ready
        if(wid==0){
            unsigned v;
            do{ v=ld_flag(&g_ready[t]); } while(__any_sync(0xffffffffu, v<4u));
        }
        __syncthreads();
        // P for finalized ng
        size_t oa=(size_t)t*BH+(size_t)rg*HHID+cf;
        float2 P0=__ldcg((const float2*)(out+oa));
        float2 P1=__ldcg((const float2*)(out+oa+8*HHID));
        // A fragments: 8 ks, full MLP
        uint4 fA1[8],fA2[8];
        #pragma unroll
        for(int j=0;j<8;j++){
            fA1[j]=__ldcg(Fp1+fo+j*32);
            fA2[j]=__ldcg(Fp2+fo+j*32);
        }
        float acc[4][4];
        #pragma unroll
        for(int n=0;n<4;n++){acc[n][0]=0.f;acc[n][1]=0.f;acc[n][2]=0.f;acc[n][3]=0.f;}
        #pragma unroll
        for(int j=0;j<8;j++){
            int ks=kq*8+j;
            #pragma unroll
            for(int n=0;n<4;n++){
                uint2 w1=Bp1[n][ks*32], w2=Bp2[n][ks*32];
                mma4(acc[n][0],acc[n][1],acc[n][2],acc[n][3],
                     fA1[j].x,fA1[j].y,fA1[j].z,fA1[j].w, w1.x,w1.y);
                mma4(acc[n][0],acc[n][1],acc[n][2],acc[n][3],
                     fA1[j].x,fA1[j].y,fA1[j].z,fA1[j].w, w2.x,w2.y);
                mma4(acc[n][0],acc[n][1],acc[n][2],acc[n][3],
                     fA2[j].x,fA2[j].y,fA2[j].z,fA2[j].w, w1.x,w1.y);
            }
        }
        // split-K exchange
        #pragma unroll
        for(int n=0;n<4;n++)
            red[(wid*4+n)*32+lane]=make_float4(acc[n][0],acc[n][1],acc[n][2],acc[n][3]);
        __syncthreads();
        float4 s=red[(p*4*4+kq)*32+lane];
        #pragma unroll
        for(int k2=1;k2<4;k2++){
            float4 q=red[((p*4+k2)*4+kq)*32+lane];
            s.x+=q.x; s.y+=q.y; s.z+=q.z; s.w+=q.w;
        }
        // finalize
        float v0=tanhf(P0.x+bias0+s.x);
        float v1=tanhf(P0.y+bias1+s.y);
        float v2=tanhf(P1.x+bias0+s.z);
        float v3=tanhf(P1.y+bias1+s.w);
        uint2 H,L;
        split2(v0,v1,H.x,L.x);
        split2(v2,v3,H.y,L.y);
        *(uint2*)(w1base+(size_t)ws*slotstride)=H;
        *(uint2*)(w2base+(size_t)ws*slotstride)=L;
        // barrier: release + poll 8 flags in domain
        __syncthreads();
        if(tid==0){ st_release(&g_flag2[domain][cta8*32],(unsigned)(i+1)); }
        // out stores after flag (consumed only by fin)
        *(float2*)(out+oa)=make_float2(v0,v1);
        *(float2*)(out+oa+8*HHID)=make_float2(v2,v3);
        if(wid==0){
            const unsigned* fp=&g_flag2[domain][(lane&7)*32];
            unsigned vv;
            do { vv=ld_flag(fp); } while(!__all_sync(0xffffffffu, vv>(unsigned)i));
        }
        __syncthreads();
    }
    if(tid==0) red_release(&g_done,1u);
}

// ---- fin ----
__global__ __launch_bounds__(256) void fin_kernel(
    const float* __restrict__ W_embed,const float* __restrict__ b_embed,
    float* __restrict__ out){
    __shared__ float hsr[HHID];
    int b=blockIdx.x, e=threadIdx.x;
    hsr[e]=out[(size_t)2046*BH+(size_t)b*HHID+e];
    hsr[e+256]=out[(size_t)2046*BH+(size_t)b*HHID+e+256];
    out[OUT_HT+(size_t)b*HHID+e]=out[(size_t)2047*BH+(size_t)b*HHID+e];
    out[OUT_HT+(size_t)b*HHID+e+256]=out[(size_t)2047*BH+(size_t)b*HHID+e+256];
    __syncthreads();
    float acc=b_embed[e];
    const float* we=W_embed+(size_t)e*HHID;
    #pragma unroll 4
    for(int h=0;h<HHID;h++) acc=fmaf(hsr[h],we[h],acc);
    out[OUT_MT+(size_t)b*EEMB+e]=acc;
}

extern "C" void kernel_launch(void* const* d_in,const int* in_sizes,int n_in,
                              void* d_out,int out_size){
    const float* input_seq=(const float*)d_in[0];
    const float* h_0=(const float*)d_in[1];
    const float* m_0=(const float*)d_in[2];
    const float* W_embed=(const float*)d_in[3];
    const float* b_embed=(const float*)d_in[4];
    const float* W_ih=(const float*)d_in[5];
    const float* b_ih=(const float*)d_in[6];
    float* out=(float*)d_out;

    cudaFuncSetAttribute(fused_kernel,cudaFuncAttributeMaxDynamicSharedMemorySize,REC_SMEM);
    prep_kernel<<<HHID,256>>>(W_ih,W_embed,b_ih,b_embed);
    boot_kernel<<<HHID,64>>>(input_seq,h_0,m_0,W_ih,b_ih,out);
    fused_kernel<<<NREC+NWORK,256,REC_SMEM>>>(input_seq,W_ih,out);
    fin_kernel<<<BB,256>>>(W_embed,b_embed,out);
}